// round 7
// baseline (speedup 1.0000x reference)
#include <cuda_runtime.h>

#define NB 8
#define NC 10
#define NH 192
#define NW 192
#define HW (NH*NW)
#define CHW (NC*HW)

#define WPAD 12

// k2 tiling: block (16,16) = 256 threads, each thread 2 output px along x.
#define OUT_W 32
#define OUT_H 16
#define IN_W 34
#define IN_H 18
#define ROWP 36                  /* padded row (floats) */
#define CH_STRIDE (IN_H*ROWP)    /* 648 */
#define REAL_ELEMS (IN_H*IN_W)   /* 612 */
#define TOT_ELEMS (10*REAL_ELEMS)/* 6120 */
#define NLD 24                   /* ceil(6120/256) */

// dynamic smem layout (floats)
#define OFF_WDT 0
#define OFF_WCT 2160
#define OFF_TA  4320
#define OFF_TB  10800
#define OFF_PAR 17280
#define SMEM_FLOATS 17584
#define SMEM_BYTES (SMEM_FLOATS*4)

// param offsets within s_par
#define P_GD 0
#define P_BED 10
#define P_GC 20
#define P_BEC 30
#define P_GG 40
#define P_BEG 50
#define P_WG 60
#define P_BG 100
#define P_WC 102

// ---------------- scratch (static device globals; no allocation) ----------------
__device__ float g_a1[NB*CHW];       // f1 * att[:,1]
__device__ float g_a2[NB*CHW];       // f1 * att[:,2]
__device__ float g_pm[6*NB*CHW];     // parts 1..6 premultiplied by their comp map

__device__ __forceinline__ float sigmoidf_(float x){ return 1.0f/(1.0f+expf(-x)); }

__device__ __forceinline__ float4 f4fma(float s, float4 v, float4 a){
    return make_float4(fmaf(s,v.x,a.x), fmaf(s,v.y,a.y), fmaf(s,v.z,a.z), fmaf(s,v.w,a.w));
}
__device__ __forceinline__ float4 f4s(float s){ return make_float4(s,s,s,s); }

// ================= Kernel 1: pointwise attention / maps / premult + slot0 copy =================
__global__ __launch_bounds__(256) void k1_pointwise(
    const float* __restrict__ f_nodes,
    const float* __restrict__ h_nodes,
    const float* __restrict__ p_nodes,
    const float* __restrict__ w_dmap, const float* __restrict__ b_dmap,
    const float* __restrict__ w_cau,  const float* __restrict__ b_cau,
    const float* __restrict__ w_cal,  const float* __restrict__ b_cal,
    float* __restrict__ out_decomp, float* __restrict__ out_cmu, float* __restrict__ out_cml,
    float* __restrict__ out_xh)
{
    __shared__ float s_wd[90], s_bd[3], s_wcau[40], s_wcal[20], s_bc[2];
    int t = threadIdx.x;
    if (t < 90)              s_wd[t]        = w_dmap[t];
    if (t >= 96 && t < 99)   s_bd[t-96]     = b_dmap[t-96];
    if (t >= 128 && t < 168) s_wcau[t-128]  = w_cau[t-128];
    if (t >= 192 && t < 212) s_wcal[t-192]  = w_cal[t-192];
    if (t == 224) s_bc[0] = b_cau[0];
    if (t == 225) s_bc[1] = b_cal[0];
    __syncthreads();

    int pix = (blockIdx.x*256 + t)*4;
    int b = pix / HW, p = pix - b*HW;

    const float* f1b = f_nodes + (size_t)(1*NB + b)*CHW + p;
    const float* h1b = h_nodes + (size_t)(1*NB + b)*CHW + p;
    const float* h2b = h_nodes + (size_t)(2*NB + b)*CHW + p;

    float4 f[10];
    float4 dm0 = f4s(s_bd[0]), dm1 = f4s(s_bd[1]), dm2 = f4s(s_bd[2]);
    #pragma unroll
    for (int c=0;c<10;c++){
        f[c]       = *(const float4*)(f1b + c*HW);
        float4 u1  = *(const float4*)(h1b + c*HW);
        float4 u2  = *(const float4*)(h2b + c*HW);
        dm0 = f4fma(s_wd[ 0+c],f[c],dm0); dm0 = f4fma(s_wd[10+c],u1,dm0); dm0 = f4fma(s_wd[20+c],u2,dm0);
        dm1 = f4fma(s_wd[30+c],f[c],dm1); dm1 = f4fma(s_wd[40+c],u1,dm1); dm1 = f4fma(s_wd[50+c],u2,dm1);
        dm2 = f4fma(s_wd[60+c],f[c],dm2); dm2 = f4fma(s_wd[70+c],u1,dm2); dm2 = f4fma(s_wd[80+c],u2,dm2);
    }

    float4 att1, att2;
    {
        float d0v[4] = {dm0.x,dm0.y,dm0.z,dm0.w};
        float d1v[4] = {dm1.x,dm1.y,dm1.z,dm1.w};
        float d2v[4] = {dm2.x,dm2.y,dm2.z,dm2.w};
        float a1v[4], a2v[4];
        #pragma unroll
        for (int i=0;i<4;i++){
            float mx = fmaxf(d0v[i], fmaxf(d1v[i], d2v[i]));
            float e0 = expf(d0v[i]-mx), e1 = expf(d1v[i]-mx), e2 = expf(d2v[i]-mx);
            float inv = 1.0f/(e0+e1+e2);
            a1v[i] = e1*inv; a2v[i] = e2*inv;
        }
        att1 = make_float4(a1v[0],a1v[1],a1v[2],a1v[3]);
        att2 = make_float4(a2v[0],a2v[1],a2v[2],a2v[3]);
    }

    float* a1p = g_a1 + (size_t)b*CHW + p;
    float* a2p = g_a2 + (size_t)b*CHW + p;
    #pragma unroll
    for (int c=0;c<10;c++){
        *(float4*)(a1p + c*HW) = make_float4(f[c].x*att1.x, f[c].y*att1.y, f[c].z*att1.z, f[c].w*att1.w);
        *(float4*)(a2p + c*HW) = make_float4(f[c].x*att2.x, f[c].y*att2.y, f[c].z*att2.z, f[c].w*att2.w);
    }

    *(float4*)(out_decomp + (size_t)(b*3+0)*HW + p) = dm0;
    *(float4*)(out_decomp + (size_t)(b*3+1)*HW + p) = dm1;
    *(float4*)(out_decomp + (size_t)(b*3+2)*HW + p) = dm2;

    // comp_map_u over parts 1..4
    float4 su = f4s(s_bc[0]);
    #pragma unroll
    for (int j=0;j<4;j++){
        const float* pp = p_nodes + (size_t)((j+1)*NB + b)*CHW + p;
        #pragma unroll
        for (int c=0;c<10;c++) su = f4fma(s_wcau[j*10+c], *(const float4*)(pp + c*HW), su);
    }
    float4 mu = make_float4(sigmoidf_(su.x), sigmoidf_(su.y), sigmoidf_(su.z), sigmoidf_(su.w));
    *(float4*)(out_cmu + (size_t)b*HW + p) = mu;

    // comp_map_l over parts 5..6
    float4 sl = f4s(s_bc[1]);
    #pragma unroll
    for (int j=0;j<2;j++){
        const float* pp = p_nodes + (size_t)((j+5)*NB + b)*CHW + p;
        #pragma unroll
        for (int c=0;c<10;c++) sl = f4fma(s_wcal[j*10+c], *(const float4*)(pp + c*HW), sl);
    }
    float4 ml = make_float4(sigmoidf_(sl.x), sigmoidf_(sl.y), sigmoidf_(sl.z), sigmoidf_(sl.w));
    *(float4*)(out_cml + (size_t)b*HW + p) = ml;

    // premultiplied parts: g_pm[j] = part_{j+1} * map  (j=0..3 upper, 4..5 lower)
    #pragma unroll
    for (int j=0;j<4;j++){
        const float* pp = p_nodes + (size_t)((j+1)*NB + b)*CHW + p;
        float* od = g_pm + (size_t)(j*NB + b)*CHW + p;
        #pragma unroll
        for (int c=0;c<10;c++){
            float4 v = *(const float4*)(pp + c*HW);
            *(float4*)(od + c*HW) = make_float4(v.x*mu.x, v.y*mu.y, v.z*mu.z, v.w*mu.w);
        }
    }
    #pragma unroll
    for (int j=0;j<2;j++){
        const float* pp = p_nodes + (size_t)((j+5)*NB + b)*CHW + p;
        float* od = g_pm + (size_t)((4+j)*NB + b)*CHW + p;
        #pragma unroll
        for (int c=0;c<10;c++){
            float4 v = *(const float4*)(pp + c*HW);
            *(float4*)(od + c*HW) = make_float4(v.x*ml.x, v.y*ml.y, v.z*ml.z, v.w*ml.w);
        }
    }

    // slot-0 copy
    const float* h0 = h_nodes + (size_t)b*CHW + p;
    float* o0 = out_xh + (size_t)b*CHW + p;
    #pragma unroll
    for (int c=0;c<10;c++) *(float4*)(o0 + c*HW) = *(const float4*)(h0 + c*HW);
}

// ================= Kernel 2 helpers =================
// cp.async one 10-channel haloed tile into smem; OOB cells zero-filled via src-size=0
__device__ __forceinline__ void stage_async(float* sbuf, const float* __restrict__ src,
                                            int tid, int x0, int y0)
{
    unsigned sbase = (unsigned)__cvta_generic_to_shared(sbuf);
    #pragma unroll
    for (int j=0;j<NLD;j++){
        int i = tid + j*256;
        if (i < TOT_ELEMS){
            int ci = i/REAL_ELEMS, rem = i - ci*REAL_ELEMS;
            int r = rem/IN_W, c = rem - r*IN_W;
            int gy = y0-1+r, gx = x0-1+c;
            bool in = (gy>=0) & (gy<NH) & (gx>=0) & (gx<NW);
            const float* g = src + (size_t)ci*HW + (in ? (gy*NW+gx) : 0);
            unsigned daddr = sbase + (unsigned)((ci*CH_STRIDE + r*ROWP + c)*4);
            int ssz = in ? 4 : 0;
            asm volatile("cp.async.ca.shared.global [%0], [%1], 4, %2;"
                         :: "r"(daddr), "l"(g), "r"(ssz));
        }
    }
    asm volatile("cp.async.commit_group;");
}
__device__ __forceinline__ void cp_wait0(){ asm volatile("cp.async.wait_group 0;" ::: "memory"); }

// load 3x4 input patch (two px share it) as 6x LDS.64
__device__ __forceinline__ void loadv(float v[3][4], const float* tb){
    #pragma unroll
    for (int dy=0;dy<3;dy++){
        float2 a = *(const float2*)(tb + dy*ROWP);
        float2 b = *(const float2*)(tb + dy*ROWP + 2);
        v[dy][0]=a.x; v[dy][1]=a.y; v[dy][2]=b.x; v[dy][3]=b.y;
    }
}

// 9 taps x 10 outs x 2 px
__device__ __forceinline__ void convk(float aL[10], float aR[10],
                                      const float v[3][4], const float* wb)
{
    #pragma unroll
    for (int k=0;k<9;k++){
        int dy=k/3, dx=k-dy*3;
        const float* wk = wb + k*WPAD;
        float4 w0 = *(const float4*)(wk);
        float4 w1 = *(const float4*)(wk+4);
        float2 w2 = *(const float2*)(wk+8);
        float vL = v[dy][dx], vR = v[dy][dx+1];
        aL[0]=fmaf(w0.x,vL,aL[0]); aR[0]=fmaf(w0.x,vR,aR[0]);
        aL[1]=fmaf(w0.y,vL,aL[1]); aR[1]=fmaf(w0.y,vR,aR[1]);
        aL[2]=fmaf(w0.z,vL,aL[2]); aR[2]=fmaf(w0.z,vR,aR[2]);
        aL[3]=fmaf(w0.w,vL,aL[3]); aR[3]=fmaf(w0.w,vR,aR[3]);
        aL[4]=fmaf(w1.x,vL,aL[4]); aR[4]=fmaf(w1.x,vR,aR[4]);
        aL[5]=fmaf(w1.y,vL,aL[5]); aR[5]=fmaf(w1.y,vR,aR[5]);
        aL[6]=fmaf(w1.z,vL,aL[6]); aR[6]=fmaf(w1.z,vR,aR[6]);
        aL[7]=fmaf(w1.w,vL,aL[7]); aR[7]=fmaf(w1.w,vR,aR[7]);
        aL[8]=fmaf(w2.x,vL,aL[8]); aR[8]=fmaf(w2.x,vR,aR[8]);
        aL[9]=fmaf(w2.y,vL,aL[9]); aR[9]=fmaf(w2.y,vR,aR[9]);
    }
}

__device__ __forceinline__ void conv_pass(float aL[10], float aR[10],
                                          const float* tiles, const float* swt,
                                          int tx, int ty)
{
    const float* tb0 = tiles + ty*ROWP + tx*2;
    #pragma unroll 1
    for (int ci=0;ci<10;ci++){
        float v[3][4];
        loadv(v, tb0 + ci*CH_STRIDE);
        convk(aL, aR, v, swt + ci*9*WPAD);
    }
}

// ================= Kernel 2: fused 3x3 convs + GRU =================
__global__ __launch_bounds__(256,2) void k2_conv(
    const float* __restrict__ h_nodes,
    const float* __restrict__ w_decomp, const float* __restrict__ g_decomp, const float* __restrict__ be_decomp,
    const float* __restrict__ w_cu, const float* __restrict__ g_cu, const float* __restrict__ be_cu,
    const float* __restrict__ w_cl, const float* __restrict__ g_cl, const float* __restrict__ be_cl,
    const float* __restrict__ wg_u, const float* __restrict__ bg_u,
    const float* __restrict__ wc_u, const float* __restrict__ g_u, const float* __restrict__ be_u,
    const float* __restrict__ wg_l, const float* __restrict__ bg_l,
    const float* __restrict__ wc_l, const float* __restrict__ g_l, const float* __restrict__ be_l,
    float* __restrict__ out_xh)
{
    extern __shared__ float smem[];
    float* s_wdt = smem + OFF_WDT;
    float* s_wct = smem + OFF_WCT;
    float* s_tA  = smem + OFF_TA;
    float* s_tB  = smem + OFF_TB;
    float* s_par = smem + OFF_PAR;

    int z = blockIdx.z; int b = z >> 1; int half = z & 1;
    const float* wc   = half ? w_cl  : w_cu;
    const float* gcv  = half ? g_cl  : g_cu;
    const float* becv = half ? be_cl : be_cu;
    const float* aX   = (half ? g_a2 : g_a1) + (size_t)b*CHW;
    const float* hX   = h_nodes + (size_t)((half?2:1)*NB + b)*CHW;
    const float* wgv  = half ? wg_l : wg_u;
    const float* bgv  = half ? bg_l : bg_u;
    const float* wcv  = half ? wc_l : wc_u;
    const float* ggv  = half ? g_l  : g_u;
    const float* bev  = half ? be_l : be_u;
    float* outp       = out_xh + (size_t)((half?2:1)*NB + b)*CHW;
    int nparts = half ? 2 : 4;
    int pidx0  = half ? 4 : 0;       // index into g_pm

    int tx = threadIdx.x, ty = threadIdx.y;
    int tid = ty*16 + tx;
    int x0 = blockIdx.x*OUT_W, y0 = blockIdx.y*OUT_H;

    // ---- weight + param staging ----
    for (int i=tid; i<1800; i+=256){
        int o = i/180, r = i - o*180, c = r/9, k = r - c*9;
        s_wdt[(c*9+k)*WPAD + o] = w_decomp[i];
        s_wct[(c*9+k)*WPAD + o] = wc[i];
    }
    if (tid < 10){
        s_par[P_GD+tid]=g_decomp[tid]; s_par[P_BED+tid]=be_decomp[tid];
        s_par[P_GC+tid]=gcv[tid];      s_par[P_BEC+tid]=becv[tid];
        s_par[P_GG+tid]=ggv[tid];      s_par[P_BEG+tid]=bev[tid];
    }
    if (tid >= 32 && tid < 72) s_par[P_WG + tid-32] = wgv[tid-32];
    if (tid == 72) { s_par[P_BG]=bgv[0]; s_par[P_BG+1]=bgv[1]; }
    for (int i=tid; i<200; i+=256) s_par[P_WC+i] = wcv[i];

    // ---- stage 1: a-tile -> A ----
    stage_async(s_tA, aX, tid, x0, y0);
    cp_wait0();
    __syncthreads();

    // ---- stage 2: issue h -> B; convD(0:10) on A ----
    stage_async(s_tB, hX, tid, x0, y0);
    float accDL[10], accDR[10];
    #pragma unroll
    for (int o=0;o<10;o++){ accDL[o]=0.0f; accDR[o]=0.0f; }
    conv_pass(accDL, accDR, s_tA, s_wdt, tx, ty);          // w_decomp[:, 0:10] * (f*att)
    cp_wait0();
    __syncthreads();

    // ---- stage 3: issue pm0 -> A; two passes on B ----
    stage_async(s_tA, g_pm + (size_t)(pidx0*NB + b)*CHW, tid, x0, y0);
    conv_pass(accDL, accDR, s_tB, s_wdt + 1080, tx, ty);   // w_decomp[:, 10:20] * h

    float msgL[10], msgR[10];
    #pragma unroll
    for (int o=0;o<10;o++){
        msgL[o] = fmaxf(fmaf(s_par[P_GD+o], accDL[o], s_par[P_BED+o]), 0.0f);
        msgR[o] = fmaxf(fmaf(s_par[P_GD+o], accDR[o], s_par[P_BED+o]), 0.0f);
    }

    float accAL[10], accAR[10];
    #pragma unroll
    for (int o=0;o<10;o++){ accAL[o]=0.0f; accAR[o]=0.0f; }
    conv_pass(accAL, accAR, s_tB, s_wct, tx, ty);          // shared: w_c[:, 0:10] * h
    cp_wait0();
    __syncthreads();

    // ---- part loop (ping-pong A/B; tiles already premultiplied) ----
    for (int part=0; part<nparts; part++){
        const float* cur = (part & 1) ? s_tB : s_tA;
        float* next      = (part & 1) ? s_tA : s_tB;
        bool more = (part+1 < nparts);
        if (more)
            stage_async(next, g_pm + (size_t)((pidx0+part+1)*NB + b)*CHW, tid, x0, y0);
        float aL[10], aR[10];
        #pragma unroll
        for (int o=0;o<10;o++){ aL[o]=accAL[o]; aR[o]=accAR[o]; }
        conv_pass(aL, aR, cur, s_wct + 1080, tx, ty);      // w_c[:, 10:20] * (p*map)
        #pragma unroll
        for (int o=0;o<10;o++){
            msgL[o] += fmaxf(fmaf(s_par[P_GC+o], aL[o], s_par[P_BEC+o]), 0.0f);
            msgR[o] += fmaxf(fmaf(s_par[P_GC+o], aR[o], s_par[P_BEC+o]), 0.0f);
        }
        if (more){
            cp_wait0();
            __syncthreads();
        }
    }

    // ---------- GRU epilogue (2 px); h center re-read from global (L2-hot) ----------
    float hcenL[10], hcenR[10];
    {
        const float* hc = hX + (size_t)(y0+ty)*NW + x0 + tx*2;
        #pragma unroll
        for (int ci=0; ci<10; ci++){
            float2 hv = *(const float2*)(hc + (size_t)ci*HW);
            hcenL[ci]=hv.x; hcenR[ci]=hv.y;
        }
    }

    float g0L=s_par[P_BG], g1L=s_par[P_BG+1], g0R=s_par[P_BG], g1R=s_par[P_BG+1];
    #pragma unroll
    for (int c=0;c<10;c++){
        float wm0=s_par[P_WG+c], wh0=s_par[P_WG+10+c], wm1=s_par[P_WG+20+c], wh1=s_par[P_WG+30+c];
        g0L = fmaf(wm0, msgL[c], g0L); g0L = fmaf(wh0, hcenL[c], g0L);
        g1L = fmaf(wm1, msgL[c], g1L); g1L = fmaf(wh1, hcenL[c], g1L);
        g0R = fmaf(wm0, msgR[c], g0R); g0R = fmaf(wh0, hcenR[c], g0R);
        g1R = fmaf(wm1, msgR[c], g1R); g1R = fmaf(wh1, hcenR[c], g1R);
    }
    float rL = sigmoidf_(g0L), uL = sigmoidf_(g1L);
    float rR = sigmoidf_(g0R), uR = sigmoidf_(g1R);
    float rhL[10], rhR[10];
    #pragma unroll
    for (int c=0;c<10;c++){ rhL[c]=rL*hcenL[c]; rhR[c]=rR*hcenR[c]; }

    float* op = outp + (size_t)(y0+ty)*NW + x0 + tx*2;
    #pragma unroll
    for (int o=0;o<10;o++){
        float sL = 0.0f, sR = 0.0f;
        #pragma unroll
        for (int c=0;c<10;c++){
            float wm = s_par[P_WC + o*20 + c];
            float wh = s_par[P_WC + o*20 + 10 + c];
            sL = fmaf(wm, msgL[c], sL); sL = fmaf(wh, rhL[c], sL);
            sR = fmaf(wm, msgR[c], sR); sR = fmaf(wh, rhR[c], sR);
        }
        float cnL = fmaf(s_par[P_GG+o], sL, s_par[P_BEG+o]);
        float cnR = fmaf(s_par[P_GG+o], sR, s_par[P_BEG+o]);
        cnL = cnL > 0.0f ? cnL : 0.01f*cnL;
        cnR = cnR > 0.0f ? cnR : 0.01f*cnR;
        float2 outv;
        outv.x = (1.0f-uL)*hcenL[o] + uL*cnL;
        outv.y = (1.0f-uR)*hcenR[o] + uR*cnR;
        *(float2*)(op + (size_t)o*HW) = outv;
    }
}

// ================= launcher =================
extern "C" void kernel_launch(void* const* d_in, const int* in_sizes, int n_in,
                              void* d_out, int out_size)
{
    const float* f_nodes  = (const float*)d_in[0];
    const float* h_nodes  = (const float*)d_in[1];
    const float* p_nodes  = (const float*)d_in[2];
    const float* w_dmap   = (const float*)d_in[4];
    const float* b_dmap   = (const float*)d_in[5];
    const float* w_decomp = (const float*)d_in[6];
    const float* g_decomp = (const float*)d_in[7];
    const float* be_decomp= (const float*)d_in[8];
    const float* w_cau    = (const float*)d_in[9];
    const float* b_cau    = (const float*)d_in[10];
    const float* w_cal    = (const float*)d_in[11];
    const float* b_cal    = (const float*)d_in[12];
    const float* w_cu     = (const float*)d_in[13];
    const float* g_cu     = (const float*)d_in[14];
    const float* be_cu    = (const float*)d_in[15];
    const float* w_cl     = (const float*)d_in[16];
    const float* g_cl     = (const float*)d_in[17];
    const float* be_cl    = (const float*)d_in[18];
    const float* wg_u     = (const float*)d_in[19];
    const float* bg_u     = (const float*)d_in[20];
    const float* wc_u     = (const float*)d_in[21];
    const float* g_u      = (const float*)d_in[22];
    const float* be_u     = (const float*)d_in[23];
    const float* wg_l     = (const float*)d_in[24];
    const float* bg_l     = (const float*)d_in[25];
    const float* wc_l     = (const float*)d_in[26];
    const float* g_l      = (const float*)d_in[27];
    const float* be_l     = (const float*)d_in[28];

    float* out        = (float*)d_out;
    float* out_decomp = out + (size_t)3*NB*CHW;
    float* out_cmu    = out_decomp + (size_t)NB*3*HW;
    float* out_cml    = out_cmu + (size_t)NB*HW;

    k1_pointwise<<<NB*HW/1024, 256>>>(f_nodes, h_nodes, p_nodes,
                                      w_dmap, b_dmap, w_cau, b_cau, w_cal, b_cal,
                                      out_decomp, out_cmu, out_cml, out);

    static int smem_set = 0;
    if (!smem_set){
        cudaFuncSetAttribute(k2_conv, cudaFuncAttributeMaxDynamicSharedMemorySize, SMEM_BYTES);
        smem_set = 1;
    }
    dim3 g2(NW/OUT_W, NH/OUT_H, 2*NB), b2(16, 16);
    k2_conv<<<g2, b2, SMEM_BYTES>>>(h_nodes,
                                    w_decomp, g_decomp, be_decomp,
                                    w_cu, g_cu, be_cu,
                                    w_cl, g_cl, be_cl,
                                    wg_u, bg_u, wc_u, g_u, be_u,
                                    wg_l, bg_l, wc_l, g_l, be_l,
                                    out);
}

// round 8
// speedup vs baseline: 1.8207x; 1.8207x over previous
#include <cuda_runtime.h>

#define NB 8
#define NC 10
#define NH 192
#define NW 192
#define HW (NH*NW)
#define CHW (NC*HW)

#define WPAD 12

// k2 tiling: block (16,16) = 256 threads, each thread 2 output px along x.
#define OUT_W 32
#define OUT_H 16
#define ROWP 40                  /* row covers gx in [x0-4, x0+36), float4-aligned */
#define NROWS 18
#define CH_STRIDE (NROWS*ROWP)   /* 720 */
#define NCHUNK (10*NROWS*10)     /* 1800 float4 chunks per tile */

// dynamic smem layout (floats)
#define OFF_WDT 0
#define OFF_WCT 2160
#define OFF_T0  4320
#define OFF_T1  (OFF_T0 + 7200)
#define OFF_T2  (OFF_T1 + 7200)
#define OFF_PAR (OFF_T2 + 7200)
#define SMEM_FLOATS (OFF_PAR + 304)
#define SMEM_BYTES (SMEM_FLOATS*4)

// param offsets within s_par
#define P_GD 0
#define P_BED 10
#define P_GC 20
#define P_BEC 30
#define P_GG 40
#define P_BEG 50
#define P_WG 60
#define P_BG 100
#define P_WC 102

// ---------------- scratch (static device globals; no allocation) ----------------
__device__ __align__(16) float g_a1[NB*CHW];       // f1 * att[:,1]
__device__ __align__(16) float g_a2[NB*CHW];       // f1 * att[:,2]
__device__ __align__(16) float g_pm[6*NB*CHW];     // parts 1..6 premultiplied by comp map

__device__ __forceinline__ float sigmoidf_(float x){ return 1.0f/(1.0f+expf(-x)); }

__device__ __forceinline__ float4 f4fma(float s, float4 v, float4 a){
    return make_float4(fmaf(s,v.x,a.x), fmaf(s,v.y,a.y), fmaf(s,v.z,a.z), fmaf(s,v.w,a.w));
}
__device__ __forceinline__ float4 f4s(float s){ return make_float4(s,s,s,s); }

// ================= Kernel 1: pointwise attention / maps / premult + slot0 copy =================
__global__ __launch_bounds__(256) void k1_pointwise(
    const float* __restrict__ f_nodes,
    const float* __restrict__ h_nodes,
    const float* __restrict__ p_nodes,
    const float* __restrict__ w_dmap, const float* __restrict__ b_dmap,
    const float* __restrict__ w_cau,  const float* __restrict__ b_cau,
    const float* __restrict__ w_cal,  const float* __restrict__ b_cal,
    float* __restrict__ out_decomp, float* __restrict__ out_cmu, float* __restrict__ out_cml,
    float* __restrict__ out_xh)
{
    __shared__ float s_wd[90], s_bd[3], s_wcau[40], s_wcal[20], s_bc[2];
    int t = threadIdx.x;
    if (t < 90)              s_wd[t]        = w_dmap[t];
    if (t >= 96 && t < 99)   s_bd[t-96]     = b_dmap[t-96];
    if (t >= 128 && t < 168) s_wcau[t-128]  = w_cau[t-128];
    if (t >= 192 && t < 212) s_wcal[t-192]  = w_cal[t-192];
    if (t == 224) s_bc[0] = b_cau[0];
    if (t == 225) s_bc[1] = b_cal[0];
    __syncthreads();

    int pix = (blockIdx.x*256 + t)*4;
    int b = pix / HW, p = pix - b*HW;

    const float* f1b = f_nodes + (size_t)(1*NB + b)*CHW + p;
    const float* h1b = h_nodes + (size_t)(1*NB + b)*CHW + p;
    const float* h2b = h_nodes + (size_t)(2*NB + b)*CHW + p;

    float4 f[10];
    float4 dm0 = f4s(s_bd[0]), dm1 = f4s(s_bd[1]), dm2 = f4s(s_bd[2]);
    #pragma unroll
    for (int c=0;c<10;c++){
        f[c]       = *(const float4*)(f1b + c*HW);
        float4 u1  = *(const float4*)(h1b + c*HW);
        float4 u2  = *(const float4*)(h2b + c*HW);
        dm0 = f4fma(s_wd[ 0+c],f[c],dm0); dm0 = f4fma(s_wd[10+c],u1,dm0); dm0 = f4fma(s_wd[20+c],u2,dm0);
        dm1 = f4fma(s_wd[30+c],f[c],dm1); dm1 = f4fma(s_wd[40+c],u1,dm1); dm1 = f4fma(s_wd[50+c],u2,dm1);
        dm2 = f4fma(s_wd[60+c],f[c],dm2); dm2 = f4fma(s_wd[70+c],u1,dm2); dm2 = f4fma(s_wd[80+c],u2,dm2);
    }

    float4 att1, att2;
    {
        float d0v[4] = {dm0.x,dm0.y,dm0.z,dm0.w};
        float d1v[4] = {dm1.x,dm1.y,dm1.z,dm1.w};
        float d2v[4] = {dm2.x,dm2.y,dm2.z,dm2.w};
        float a1v[4], a2v[4];
        #pragma unroll
        for (int i=0;i<4;i++){
            float mx = fmaxf(d0v[i], fmaxf(d1v[i], d2v[i]));
            float e0 = expf(d0v[i]-mx), e1 = expf(d1v[i]-mx), e2 = expf(d2v[i]-mx);
            float inv = 1.0f/(e0+e1+e2);
            a1v[i] = e1*inv; a2v[i] = e2*inv;
        }
        att1 = make_float4(a1v[0],a1v[1],a1v[2],a1v[3]);
        att2 = make_float4(a2v[0],a2v[1],a2v[2],a2v[3]);
    }

    float* a1p = g_a1 + (size_t)b*CHW + p;
    float* a2p = g_a2 + (size_t)b*CHW + p;
    #pragma unroll
    for (int c=0;c<10;c++){
        *(float4*)(a1p + c*HW) = make_float4(f[c].x*att1.x, f[c].y*att1.y, f[c].z*att1.z, f[c].w*att1.w);
        *(float4*)(a2p + c*HW) = make_float4(f[c].x*att2.x, f[c].y*att2.y, f[c].z*att2.z, f[c].w*att2.w);
    }

    *(float4*)(out_decomp + (size_t)(b*3+0)*HW + p) = dm0;
    *(float4*)(out_decomp + (size_t)(b*3+1)*HW + p) = dm1;
    *(float4*)(out_decomp + (size_t)(b*3+2)*HW + p) = dm2;

    // comp_map_u over parts 1..4
    float4 su = f4s(s_bc[0]);
    #pragma unroll
    for (int j=0;j<4;j++){
        const float* pp = p_nodes + (size_t)((j+1)*NB + b)*CHW + p;
        #pragma unroll
        for (int c=0;c<10;c++) su = f4fma(s_wcau[j*10+c], *(const float4*)(pp + c*HW), su);
    }
    float4 mu = make_float4(sigmoidf_(su.x), sigmoidf_(su.y), sigmoidf_(su.z), sigmoidf_(su.w));
    *(float4*)(out_cmu + (size_t)b*HW + p) = mu;

    // comp_map_l over parts 5..6
    float4 sl = f4s(s_bc[1]);
    #pragma unroll
    for (int j=0;j<2;j++){
        const float* pp = p_nodes + (size_t)((j+5)*NB + b)*CHW + p;
        #pragma unroll
        for (int c=0;c<10;c++) sl = f4fma(s_wcal[j*10+c], *(const float4*)(pp + c*HW), sl);
    }
    float4 ml = make_float4(sigmoidf_(sl.x), sigmoidf_(sl.y), sigmoidf_(sl.z), sigmoidf_(sl.w));
    *(float4*)(out_cml + (size_t)b*HW + p) = ml;

    // premultiplied parts
    #pragma unroll
    for (int j=0;j<4;j++){
        const float* pp = p_nodes + (size_t)((j+1)*NB + b)*CHW + p;
        float* od = g_pm + (size_t)(j*NB + b)*CHW + p;
        #pragma unroll
        for (int c=0;c<10;c++){
            float4 v = *(const float4*)(pp + c*HW);
            *(float4*)(od + c*HW) = make_float4(v.x*mu.x, v.y*mu.y, v.z*mu.z, v.w*mu.w);
        }
    }
    #pragma unroll
    for (int j=0;j<2;j++){
        const float* pp = p_nodes + (size_t)((j+5)*NB + b)*CHW + p;
        float* od = g_pm + (size_t)((4+j)*NB + b)*CHW + p;
        #pragma unroll
        for (int c=0;c<10;c++){
            float4 v = *(const float4*)(pp + c*HW);
            *(float4*)(od + c*HW) = make_float4(v.x*ml.x, v.y*ml.y, v.z*ml.z, v.w*ml.w);
        }
    }

    // slot-0 copy
    const float* h0 = h_nodes + (size_t)b*CHW + p;
    float* o0 = out_xh + (size_t)b*CHW + p;
    #pragma unroll
    for (int c=0;c<10;c++) *(float4*)(o0 + c*HW) = *(const float4*)(h0 + c*HW);
}

// ================= Kernel 2 helpers =================
// 16B cp.async staging: 1800 float4 chunks; OOB chunks zero-filled via src-size=0.
__device__ __forceinline__ void stage_async(float* sbuf, const float* __restrict__ src,
                                            int tid, int x0, int y0)
{
    unsigned sbase = (unsigned)__cvta_generic_to_shared(sbuf);
    #pragma unroll
    for (int j=0;j<8;j++){
        int i = tid + j*256;
        if (i < NCHUNK){
            int ci = i/180, rem = i - ci*180;
            int r = rem/10, c4 = rem - r*10;
            int gy = y0-1+r, gx = x0-16+c4*4;   /* placeholder recomputed below */
            gx = x0-4+c4*4;
            bool in = (gy>=0) & (gy<NH) & (gx>=0) & (gx<NW);
            const float* g = src + (size_t)ci*HW + (in ? (gy*NW+gx) : 0);
            unsigned d = sbase + (unsigned)((ci*CH_STRIDE + r*ROWP + c4*4)*4);
            int ssz = in ? 16 : 0;
            asm volatile("cp.async.cg.shared.global [%0], [%1], 16, %2;"
                         :: "r"(d), "l"(g), "r"(ssz));
        }
    }
    asm volatile("cp.async.commit_group;");
}
__device__ __forceinline__ void cp_wait0(){ asm volatile("cp.async.wait_group 0;" ::: "memory"); }

// load the 3x4 tap patch for a pixel pair: 3 aligned LDS.64 per row, extract 4 taps
__device__ __forceinline__ void loadv(float v[3][4], const float* tb){
    #pragma unroll
    for (int dy=0;dy<3;dy++){
        float2 p0 = *(const float2*)(tb + dy*ROWP);
        float2 p1 = *(const float2*)(tb + dy*ROWP + 2);
        float2 p2 = *(const float2*)(tb + dy*ROWP + 4);
        v[dy][0]=p0.y; v[dy][1]=p1.x; v[dy][2]=p1.y; v[dy][3]=p2.x;
    }
}

// 9 taps x 10 outs x 2 px
__device__ __forceinline__ void convk(float aL[10], float aR[10],
                                      const float v[3][4], const float* wb)
{
    #pragma unroll
    for (int k=0;k<9;k++){
        int dy=k/3, dx=k-dy*3;
        const float* wk = wb + k*WPAD;
        float4 w0 = *(const float4*)(wk);
        float4 w1 = *(const float4*)(wk+4);
        float2 w2 = *(const float2*)(wk+8);
        float vL = v[dy][dx], vR = v[dy][dx+1];
        aL[0]=fmaf(w0.x,vL,aL[0]); aR[0]=fmaf(w0.x,vR,aR[0]);
        aL[1]=fmaf(w0.y,vL,aL[1]); aR[1]=fmaf(w0.y,vR,aR[1]);
        aL[2]=fmaf(w0.z,vL,aL[2]); aR[2]=fmaf(w0.z,vR,aR[2]);
        aL[3]=fmaf(w0.w,vL,aL[3]); aR[3]=fmaf(w0.w,vR,aR[3]);
        aL[4]=fmaf(w1.x,vL,aL[4]); aR[4]=fmaf(w1.x,vR,aR[4]);
        aL[5]=fmaf(w1.y,vL,aL[5]); aR[5]=fmaf(w1.y,vR,aR[5]);
        aL[6]=fmaf(w1.z,vL,aL[6]); aR[6]=fmaf(w1.z,vR,aR[6]);
        aL[7]=fmaf(w1.w,vL,aL[7]); aR[7]=fmaf(w1.w,vR,aR[7]);
        aL[8]=fmaf(w2.x,vL,aL[8]); aR[8]=fmaf(w2.x,vR,aR[8]);
        aL[9]=fmaf(w2.y,vL,aL[9]); aR[9]=fmaf(w2.y,vR,aR[9]);
    }
}

__device__ __forceinline__ void conv_pass(float aL[10], float aR[10],
                                          const float* tiles, const float* swt,
                                          int tx, int ty)
{
    const float* tb0 = tiles + ty*ROWP + tx*2 + 2;
    #pragma unroll 1
    for (int ci=0;ci<10;ci++){
        float v[3][4];
        loadv(v, tb0 + ci*CH_STRIDE);
        convk(aL, aR, v, swt + ci*9*WPAD);
    }
}

// ================= Kernel 2: fused 3x3 convs + GRU, triple-buffered cp.async =================
__global__ __launch_bounds__(256,2) void k2_conv(
    const float* __restrict__ h_nodes,
    const float* __restrict__ w_decomp, const float* __restrict__ g_decomp, const float* __restrict__ be_decomp,
    const float* __restrict__ w_cu, const float* __restrict__ g_cu, const float* __restrict__ be_cu,
    const float* __restrict__ w_cl, const float* __restrict__ g_cl, const float* __restrict__ be_cl,
    const float* __restrict__ wg_u, const float* __restrict__ bg_u,
    const float* __restrict__ wc_u, const float* __restrict__ g_u, const float* __restrict__ be_u,
    const float* __restrict__ wg_l, const float* __restrict__ bg_l,
    const float* __restrict__ wc_l, const float* __restrict__ g_l, const float* __restrict__ be_l,
    float* __restrict__ out_xh)
{
    extern __shared__ float smem[];
    float* s_wdt = smem + OFF_WDT;
    float* s_wct = smem + OFF_WCT;
    float* s_par = smem + OFF_PAR;
    float* bufs[3] = { smem + OFF_T0, smem + OFF_T1, smem + OFF_T2 };

    int z = blockIdx.z; int b = z >> 1; int half = z & 1;
    const float* wc   = half ? w_cl  : w_cu;
    const float* gcv  = half ? g_cl  : g_cu;
    const float* becv = half ? be_cl : be_cu;
    const float* aX   = (half ? g_a2 : g_a1) + (size_t)b*CHW;
    const float* hX   = h_nodes + (size_t)((half?2:1)*NB + b)*CHW;
    const float* wgv  = half ? wg_l : wg_u;
    const float* bgv  = half ? bg_l : bg_u;
    const float* wcv  = half ? wc_l : wc_u;
    const float* ggv  = half ? g_l  : g_u;
    const float* bev  = half ? be_l : be_u;
    float* outp       = out_xh + (size_t)((half?2:1)*NB + b)*CHW;
    int nparts = half ? 2 : 4;
    int pidx0  = half ? 4 : 0;

    int tx = threadIdx.x, ty = threadIdx.y;
    int tid = ty*16 + tx;
    int x0 = blockIdx.x*OUT_W, y0 = blockIdx.y*OUT_H;

    // ---- issue tile loads first (overlap with weight staging) ----
    stage_async(bufs[0], aX, tid, x0, y0);   // group: a-tile
    stage_async(bufs[1], hX, tid, x0, y0);   // group: h-tile

    // ---- weight + param staging ----
    for (int i=tid; i<1800; i+=256){
        int o = i/180, r = i - o*180, c = r/9, k = r - c*9;
        s_wdt[(c*9+k)*WPAD + o] = w_decomp[i];
        s_wct[(c*9+k)*WPAD + o] = wc[i];
    }
    if (tid < 10){
        s_par[P_GD+tid]=g_decomp[tid]; s_par[P_BED+tid]=be_decomp[tid];
        s_par[P_GC+tid]=gcv[tid];      s_par[P_BEC+tid]=becv[tid];
        s_par[P_GG+tid]=ggv[tid];      s_par[P_BEG+tid]=bev[tid];
    }
    if (tid >= 32 && tid < 72) s_par[P_WG + tid-32] = wgv[tid-32];
    if (tid == 72) { s_par[P_BG]=bgv[0]; s_par[P_BG+1]=bgv[1]; }
    for (int i=tid; i<200; i+=256) s_par[P_WC+i] = wcv[i];

    cp_wait0();
    __syncthreads();

    // ---- issue pm0 -> T2, then compute the three h/a passes ----
    stage_async(bufs[2], g_pm + (size_t)(pidx0*NB + b)*CHW, tid, x0, y0);

    float accDL[10], accDR[10];
    #pragma unroll
    for (int o=0;o<10;o++){ accDL[o]=0.0f; accDR[o]=0.0f; }
    conv_pass(accDL, accDR, bufs[0], s_wdt, tx, ty);        // w_decomp[:, 0:10] * (f*att)
    conv_pass(accDL, accDR, bufs[1], s_wdt + 1080, tx, ty); // w_decomp[:, 10:20] * h

    float msgL[10], msgR[10];
    #pragma unroll
    for (int o=0;o<10;o++){
        msgL[o] = fmaxf(fmaf(s_par[P_GD+o], accDL[o], s_par[P_BED+o]), 0.0f);
        msgR[o] = fmaxf(fmaf(s_par[P_GD+o], accDR[o], s_par[P_BED+o]), 0.0f);
    }

    float accAL[10], accAR[10];
    #pragma unroll
    for (int o=0;o<10;o++){ accAL[o]=0.0f; accAR[o]=0.0f; }
    conv_pass(accAL, accAR, bufs[1], s_wct, tx, ty);        // shared: w_c[:, 0:10] * h

    // ---- part loop: tile for part p lives in bufs[(2+p)%3]; prefetch p+1 into bufs[p%3] ----
    for (int part=0; part<nparts; part++){
        cp_wait0();            // drains the load for THIS part (only one group outstanding)
        __syncthreads();       // all threads' copies visible; all done reading recycled buffer
        if (part+1 < nparts)
            stage_async(bufs[part%3], g_pm + (size_t)((pidx0+part+1)*NB + b)*CHW, tid, x0, y0);
        const float* cur = bufs[(2+part)%3];
        float aL[10], aR[10];
        #pragma unroll
        for (int o=0;o<10;o++){ aL[o]=accAL[o]; aR[o]=accAR[o]; }
        conv_pass(aL, aR, cur, s_wct + 1080, tx, ty);       // w_c[:, 10:20] * (p*map)
        #pragma unroll
        for (int o=0;o<10;o++){
            msgL[o] += fmaxf(fmaf(s_par[P_GC+o], aL[o], s_par[P_BEC+o]), 0.0f);
            msgR[o] += fmaxf(fmaf(s_par[P_GC+o], aR[o], s_par[P_BEC+o]), 0.0f);
        }
    }

    // ---------- GRU epilogue (2 px); h center re-read from global (L2-hot) ----------
    float hcenL[10], hcenR[10];
    {
        const float* hc = hX + (size_t)(y0+ty)*NW + x0 + tx*2;
        #pragma unroll
        for (int ci=0; ci<10; ci++){
            float2 hv = *(const float2*)(hc + (size_t)ci*HW);
            hcenL[ci]=hv.x; hcenR[ci]=hv.y;
        }
    }

    float g0L=s_par[P_BG], g1L=s_par[P_BG+1], g0R=s_par[P_BG], g1R=s_par[P_BG+1];
    #pragma unroll
    for (int c=0;c<10;c++){
        float wm0=s_par[P_WG+c], wh0=s_par[P_WG+10+c], wm1=s_par[P_WG+20+c], wh1=s_par[P_WG+30+c];
        g0L = fmaf(wm0, msgL[c], g0L); g0L = fmaf(wh0, hcenL[c], g0L);
        g1L = fmaf(wm1, msgL[c], g1L); g1L = fmaf(wh1, hcenL[c], g1L);
        g0R = fmaf(wm0, msgR[c], g0R); g0R = fmaf(wh0, hcenR[c], g0R);
        g1R = fmaf(wm1, msgR[c], g1R); g1R = fmaf(wh1, hcenR[c], g1R);
    }
    float rL = sigmoidf_(g0L), uL = sigmoidf_(g1L);
    float rR = sigmoidf_(g0R), uR = sigmoidf_(g1R);
    float rhL[10], rhR[10];
    #pragma unroll
    for (int c=0;c<10;c++){ rhL[c]=rL*hcenL[c]; rhR[c]=rR*hcenR[c]; }

    float* op = outp + (size_t)(y0+ty)*NW + x0 + tx*2;
    #pragma unroll
    for (int o=0;o<10;o++){
        float sL = 0.0f, sR = 0.0f;
        #pragma unroll
        for (int c=0;c<10;c++){
            float wm = s_par[P_WC + o*20 + c];
            float wh = s_par[P_WC + o*20 + 10 + c];
            sL = fmaf(wm, msgL[c], sL); sL = fmaf(wh, rhL[c], sL);
            sR = fmaf(wm, msgR[c], sR); sR = fmaf(wh, rhR[c], sR);
        }
        float cnL = fmaf(s_par[P_GG+o], sL, s_par[P_BEG+o]);
        float cnR = fmaf(s_par[P_GG+o], sR, s_par[P_BEG+o]);
        cnL = cnL > 0.0f ? cnL : 0.01f*cnL;
        cnR = cnR > 0.0f ? cnR : 0.01f*cnR;
        float2 outv;
        outv.x = (1.0f-uL)*hcenL[o] + uL*cnL;
        outv.y = (1.0f-uR)*hcenR[o] + uR*cnR;
        *(float2*)(op + (size_t)o*HW) = outv;
    }
}

// ================= launcher =================
extern "C" void kernel_launch(void* const* d_in, const int* in_sizes, int n_in,
                              void* d_out, int out_size)
{
    const float* f_nodes  = (const float*)d_in[0];
    const float* h_nodes  = (const float*)d_in[1];
    const float* p_nodes  = (const float*)d_in[2];
    const float* w_dmap   = (const float*)d_in[4];
    const float* b_dmap   = (const float*)d_in[5];
    const float* w_decomp = (const float*)d_in[6];
    const float* g_decomp = (const float*)d_in[7];
    const float* be_decomp= (const float*)d_in[8];
    const float* w_cau    = (const float*)d_in[9];
    const float* b_cau    = (const float*)d_in[10];
    const float* w_cal    = (const float*)d_in[11];
    const float* b_cal    = (const float*)d_in[12];
    const float* w_cu     = (const float*)d_in[13];
    const float* g_cu     = (const float*)d_in[14];
    const float* be_cu    = (const float*)d_in[15];
    const float* w_cl     = (const float*)d_in[16];
    const float* g_cl     = (const float*)d_in[17];
    const float* be_cl    = (const float*)d_in[18];
    const float* wg_u     = (const float*)d_in[19];
    const float* bg_u     = (const float*)d_in[20];
    const float* wc_u     = (const float*)d_in[21];
    const float* g_u      = (const float*)d_in[22];
    const float* be_u     = (const float*)d_in[23];
    const float* wg_l     = (const float*)d_in[24];
    const float* bg_l     = (const float*)d_in[25];
    const float* wc_l     = (const float*)d_in[26];
    const float* g_l      = (const float*)d_in[27];
    const float* be_l     = (const float*)d_in[28];

    float* out        = (float*)d_out;
    float* out_decomp = out + (size_t)3*NB*CHW;
    float* out_cmu    = out_decomp + (size_t)NB*3*HW;
    float* out_cml    = out_cmu + (size_t)NB*HW;

    k1_pointwise<<<NB*HW/1024, 256>>>(f_nodes, h_nodes, p_nodes,
                                      w_dmap, b_dmap, w_cau, b_cau, w_cal, b_cal,
                                      out_decomp, out_cmu, out_cml, out);

    static int smem_set = 0;
    if (!smem_set){
        cudaFuncSetAttribute(k2_conv, cudaFuncAttributeMaxDynamicSharedMemorySize, SMEM_BYTES);
        smem_set = 1;
    }
    dim3 g2(NW/OUT_W, NH/OUT_H, 2*NB), b2(16, 16);
    k2_conv<<<g2, b2, SMEM_BYTES>>>(h_nodes,
                                    w_decomp, g_decomp, be_decomp,
                                    w_cu, g_cu, be_cu,
                                    w_cl, g_cl, be_cl,
                                    wg_u, bg_u, wc_u, g_u, be_u,
                                    wg_l, bg_l, wc_l, g_l, be_l,
                                    out);
}

// round 9
// speedup vs baseline: 1.9092x; 1.0486x over previous
#include <cuda_runtime.h>

#define NB 8
#define NC 10
#define NH 192
#define NW 192
#define HW (NH*NW)
#define CHW (NC*HW)

#define WPAD 12

// k2 tiling: block (16,16) = 256 threads, each thread 2 output px along x.
#define OUT_W 32
#define OUT_H 16
#define ROWP 40                  /* row covers gx in [x0-4, x0+36), float4-aligned */
#define NROWS 18
#define CH_STRIDE (NROWS*ROWP)   /* 720 */
#define NCHUNK (10*NROWS*10)     /* 1800 float4 chunks per tile */

// dynamic smem layout (floats)
#define OFF_WDT 0
#define OFF_WCT 2160
#define OFF_T0  4320
#define OFF_T1  (OFF_T0 + 7200)
#define OFF_T2  (OFF_T1 + 7200)
#define OFF_PAR (OFF_T2 + 7200)
#define SMEM_FLOATS (OFF_PAR + 304)
#define SMEM_BYTES (SMEM_FLOATS*4)

// param offsets within s_par
#define P_GD 0
#define P_BED 10
#define P_GC 20
#define P_BEC 30
#define P_GG 40
#define P_BEG 50
#define P_WG 60
#define P_BG 100
#define P_WC 102

// ---------------- scratch (static device globals; no allocation) ----------------
__device__ __align__(16) float g_a1[NB*CHW];       // f1 * att[:,1]
__device__ __align__(16) float g_a2[NB*CHW];       // f1 * att[:,2]
__device__ __align__(16) float g_pm[6*NB*CHW];     // parts 1..6 premultiplied by comp map

__device__ __forceinline__ float sigmoidf_(float x){ return 1.0f/(1.0f+expf(-x)); }

__device__ __forceinline__ float4 f4fma(float s, float4 v, float4 a){
    return make_float4(fmaf(s,v.x,a.x), fmaf(s,v.y,a.y), fmaf(s,v.z,a.z), fmaf(s,v.w,a.w));
}
__device__ __forceinline__ float4 f4s(float s){ return make_float4(s,s,s,s); }

// ================= Kernel 1: pointwise attention / maps / premult + slot0 copy =================
__global__ __launch_bounds__(256) void k1_pointwise(
    const float* __restrict__ f_nodes,
    const float* __restrict__ h_nodes,
    const float* __restrict__ p_nodes,
    const float* __restrict__ w_dmap, const float* __restrict__ b_dmap,
    const float* __restrict__ w_cau,  const float* __restrict__ b_cau,
    const float* __restrict__ w_cal,  const float* __restrict__ b_cal,
    float* __restrict__ out_decomp, float* __restrict__ out_cmu, float* __restrict__ out_cml,
    float* __restrict__ out_xh)
{
    __shared__ float s_wd[90], s_bd[3], s_wcau[40], s_wcal[20], s_bc[2];
    int t = threadIdx.x;
    if (t < 90)              s_wd[t]        = w_dmap[t];
    if (t >= 96 && t < 99)   s_bd[t-96]     = b_dmap[t-96];
    if (t >= 128 && t < 168) s_wcau[t-128]  = w_cau[t-128];
    if (t >= 192 && t < 212) s_wcal[t-192]  = w_cal[t-192];
    if (t == 224) s_bc[0] = b_cau[0];
    if (t == 225) s_bc[1] = b_cal[0];
    __syncthreads();

    int pix = (blockIdx.x*256 + t)*4;
    int b = pix / HW, p = pix - b*HW;

    const float* f1b = f_nodes + (size_t)(1*NB + b)*CHW + p;
    const float* h1b = h_nodes + (size_t)(1*NB + b)*CHW + p;
    const float* h2b = h_nodes + (size_t)(2*NB + b)*CHW + p;

    float4 f[10];
    float4 dm0 = f4s(s_bd[0]), dm1 = f4s(s_bd[1]), dm2 = f4s(s_bd[2]);
    #pragma unroll
    for (int c=0;c<10;c++){
        f[c]       = *(const float4*)(f1b + c*HW);
        float4 u1  = *(const float4*)(h1b + c*HW);
        float4 u2  = *(const float4*)(h2b + c*HW);
        dm0 = f4fma(s_wd[ 0+c],f[c],dm0); dm0 = f4fma(s_wd[10+c],u1,dm0); dm0 = f4fma(s_wd[20+c],u2,dm0);
        dm1 = f4fma(s_wd[30+c],f[c],dm1); dm1 = f4fma(s_wd[40+c],u1,dm1); dm1 = f4fma(s_wd[50+c],u2,dm1);
        dm2 = f4fma(s_wd[60+c],f[c],dm2); dm2 = f4fma(s_wd[70+c],u1,dm2); dm2 = f4fma(s_wd[80+c],u2,dm2);
    }

    float4 att1, att2;
    {
        float d0v[4] = {dm0.x,dm0.y,dm0.z,dm0.w};
        float d1v[4] = {dm1.x,dm1.y,dm1.z,dm1.w};
        float d2v[4] = {dm2.x,dm2.y,dm2.z,dm2.w};
        float a1v[4], a2v[4];
        #pragma unroll
        for (int i=0;i<4;i++){
            float mx = fmaxf(d0v[i], fmaxf(d1v[i], d2v[i]));
            float e0 = expf(d0v[i]-mx), e1 = expf(d1v[i]-mx), e2 = expf(d2v[i]-mx);
            float inv = 1.0f/(e0+e1+e2);
            a1v[i] = e1*inv; a2v[i] = e2*inv;
        }
        att1 = make_float4(a1v[0],a1v[1],a1v[2],a1v[3]);
        att2 = make_float4(a2v[0],a2v[1],a2v[2],a2v[3]);
    }

    float* a1p = g_a1 + (size_t)b*CHW + p;
    float* a2p = g_a2 + (size_t)b*CHW + p;
    #pragma unroll
    for (int c=0;c<10;c++){
        *(float4*)(a1p + c*HW) = make_float4(f[c].x*att1.x, f[c].y*att1.y, f[c].z*att1.z, f[c].w*att1.w);
        *(float4*)(a2p + c*HW) = make_float4(f[c].x*att2.x, f[c].y*att2.y, f[c].z*att2.z, f[c].w*att2.w);
    }

    *(float4*)(out_decomp + (size_t)(b*3+0)*HW + p) = dm0;
    *(float4*)(out_decomp + (size_t)(b*3+1)*HW + p) = dm1;
    *(float4*)(out_decomp + (size_t)(b*3+2)*HW + p) = dm2;

    // comp_map_u over parts 1..4
    float4 su = f4s(s_bc[0]);
    #pragma unroll
    for (int j=0;j<4;j++){
        const float* pp = p_nodes + (size_t)((j+1)*NB + b)*CHW + p;
        #pragma unroll
        for (int c=0;c<10;c++) su = f4fma(s_wcau[j*10+c], *(const float4*)(pp + c*HW), su);
    }
    float4 mu = make_float4(sigmoidf_(su.x), sigmoidf_(su.y), sigmoidf_(su.z), sigmoidf_(su.w));
    *(float4*)(out_cmu + (size_t)b*HW + p) = mu;

    // comp_map_l over parts 5..6
    float4 sl = f4s(s_bc[1]);
    #pragma unroll
    for (int j=0;j<2;j++){
        const float* pp = p_nodes + (size_t)((j+5)*NB + b)*CHW + p;
        #pragma unroll
        for (int c=0;c<10;c++) sl = f4fma(s_wcal[j*10+c], *(const float4*)(pp + c*HW), sl);
    }
    float4 ml = make_float4(sigmoidf_(sl.x), sigmoidf_(sl.y), sigmoidf_(sl.z), sigmoidf_(sl.w));
    *(float4*)(out_cml + (size_t)b*HW + p) = ml;

    // premultiplied parts
    #pragma unroll
    for (int j=0;j<4;j++){
        const float* pp = p_nodes + (size_t)((j+1)*NB + b)*CHW + p;
        float* od = g_pm + (size_t)(j*NB + b)*CHW + p;
        #pragma unroll
        for (int c=0;c<10;c++){
            float4 v = *(const float4*)(pp + c*HW);
            *(float4*)(od + c*HW) = make_float4(v.x*mu.x, v.y*mu.y, v.z*mu.z, v.w*mu.w);
        }
    }
    #pragma unroll
    for (int j=0;j<2;j++){
        const float* pp = p_nodes + (size_t)((j+5)*NB + b)*CHW + p;
        float* od = g_pm + (size_t)((4+j)*NB + b)*CHW + p;
        #pragma unroll
        for (int c=0;c<10;c++){
            float4 v = *(const float4*)(pp + c*HW);
            *(float4*)(od + c*HW) = make_float4(v.x*ml.x, v.y*ml.y, v.z*ml.z, v.w*ml.w);
        }
    }

    // slot-0 copy
    const float* h0 = h_nodes + (size_t)b*CHW + p;
    float* o0 = out_xh + (size_t)b*CHW + p;
    #pragma unroll
    for (int c=0;c<10;c++) *(float4*)(o0 + c*HW) = *(const float4*)(h0 + c*HW);
}

// ================= Kernel 2 helpers =================
// 16B cp.async staging: 1800 float4 chunks; OOB chunks zero-filled via src-size=0.
__device__ __forceinline__ void stage_async(float* sbuf, const float* __restrict__ src,
                                            int tid, int x0, int y0)
{
    unsigned sbase = (unsigned)__cvta_generic_to_shared(sbuf);
    #pragma unroll
    for (int j=0;j<8;j++){
        int i = tid + j*256;
        if (i < NCHUNK){
            int ci = i/180, rem = i - ci*180;
            int r = rem/10, c4 = rem - r*10;
            int gy = y0-1+r, gx = x0-16+c4*4;   /* placeholder recomputed below */
            gx = x0-4+c4*4;
            bool in = (gy>=0) & (gy<NH) & (gx>=0) & (gx<NW);
            const float* g = src + (size_t)ci*HW + (in ? (gy*NW+gx) : 0);
            unsigned d = sbase + (unsigned)((ci*CH_STRIDE + r*ROWP + c4*4)*4);
            int ssz = in ? 16 : 0;
            asm volatile("cp.async.cg.shared.global [%0], [%1], 16, %2;"
                         :: "r"(d), "l"(g), "r"(ssz));
        }
    }
    asm volatile("cp.async.commit_group;");
}
__device__ __forceinline__ void cp_wait0(){ asm volatile("cp.async.wait_group 0;" ::: "memory"); }

// load the 3x4 tap patch for a pixel pair: 3 aligned LDS.64 per row, extract 4 taps
__device__ __forceinline__ void loadv(float v[3][4], const float* tb){
    #pragma unroll
    for (int dy=0;dy<3;dy++){
        float2 p0 = *(const float2*)(tb + dy*ROWP);
        float2 p1 = *(const float2*)(tb + dy*ROWP + 2);
        float2 p2 = *(const float2*)(tb + dy*ROWP + 4);
        v[dy][0]=p0.y; v[dy][1]=p1.x; v[dy][2]=p1.y; v[dy][3]=p2.x;
    }
}

// 9 taps x 10 outs x 2 px
__device__ __forceinline__ void convk(float aL[10], float aR[10],
                                      const float v[3][4], const float* wb)
{
    #pragma unroll
    for (int k=0;k<9;k++){
        int dy=k/3, dx=k-dy*3;
        const float* wk = wb + k*WPAD;
        float4 w0 = *(const float4*)(wk);
        float4 w1 = *(const float4*)(wk+4);
        float2 w2 = *(const float2*)(wk+8);
        float vL = v[dy][dx], vR = v[dy][dx+1];
        aL[0]=fmaf(w0.x,vL,aL[0]); aR[0]=fmaf(w0.x,vR,aR[0]);
        aL[1]=fmaf(w0.y,vL,aL[1]); aR[1]=fmaf(w0.y,vR,aR[1]);
        aL[2]=fmaf(w0.z,vL,aL[2]); aR[2]=fmaf(w0.z,vR,aR[2]);
        aL[3]=fmaf(w0.w,vL,aL[3]); aR[3]=fmaf(w0.w,vR,aR[3]);
        aL[4]=fmaf(w1.x,vL,aL[4]); aR[4]=fmaf(w1.x,vR,aR[4]);
        aL[5]=fmaf(w1.y,vL,aL[5]); aR[5]=fmaf(w1.y,vR,aR[5]);
        aL[6]=fmaf(w1.z,vL,aL[6]); aR[6]=fmaf(w1.z,vR,aR[6]);
        aL[7]=fmaf(w1.w,vL,aL[7]); aR[7]=fmaf(w1.w,vR,aR[7]);
        aL[8]=fmaf(w2.x,vL,aL[8]); aR[8]=fmaf(w2.x,vR,aR[8]);
        aL[9]=fmaf(w2.y,vL,aL[9]); aR[9]=fmaf(w2.y,vR,aR[9]);
    }
}

__device__ __forceinline__ void conv_pass(float aL[10], float aR[10],
                                          const float* tiles, const float* swt,
                                          int tx, int ty)
{
    const float* tb0 = tiles + ty*ROWP + tx*2 + 2;
    #pragma unroll 1
    for (int ci=0;ci<10;ci++){
        float v[3][4];
        loadv(v, tb0 + ci*CH_STRIDE);
        convk(aL, aR, v, swt + ci*9*WPAD);
    }
}

// ================= Kernel 2: fused 3x3 convs + GRU, triple-buffered cp.async =================
__global__ __launch_bounds__(256,2) void k2_conv(
    const float* __restrict__ h_nodes,
    const float* __restrict__ w_decomp, const float* __restrict__ g_decomp, const float* __restrict__ be_decomp,
    const float* __restrict__ w_cu, const float* __restrict__ g_cu, const float* __restrict__ be_cu,
    const float* __restrict__ w_cl, const float* __restrict__ g_cl, const float* __restrict__ be_cl,
    const float* __restrict__ wg_u, const float* __restrict__ bg_u,
    const float* __restrict__ wc_u, const float* __restrict__ g_u, const float* __restrict__ be_u,
    const float* __restrict__ wg_l, const float* __restrict__ bg_l,
    const float* __restrict__ wc_l, const float* __restrict__ g_l, const float* __restrict__ be_l,
    float* __restrict__ out_xh)
{
    extern __shared__ float smem[];
    float* s_wdt = smem + OFF_WDT;
    float* s_wct = smem + OFF_WCT;
    float* s_par = smem + OFF_PAR;
    float* bufs[3] = { smem + OFF_T0, smem + OFF_T1, smem + OFF_T2 };

    int z = blockIdx.z; int b = z >> 1; int half = z & 1;
    const float* wc   = half ? w_cl  : w_cu;
    const float* gcv  = half ? g_cl  : g_cu;
    const float* becv = half ? be_cl : be_cu;
    const float* aX   = (half ? g_a2 : g_a1) + (size_t)b*CHW;
    const float* hX   = h_nodes + (size_t)((half?2:1)*NB + b)*CHW;
    const float* wgv  = half ? wg_l : wg_u;
    const float* bgv  = half ? bg_l : bg_u;
    const float* wcv  = half ? wc_l : wc_u;
    const float* ggv  = half ? g_l  : g_u;
    const float* bev  = half ? be_l : be_u;
    float* outp       = out_xh + (size_t)((half?2:1)*NB + b)*CHW;
    int nparts = half ? 2 : 4;
    int pidx0  = half ? 4 : 0;

    int tx = threadIdx.x, ty = threadIdx.y;
    int tid = ty*16 + tx;
    int x0 = blockIdx.x*OUT_W, y0 = blockIdx.y*OUT_H;

    // ---- issue tile loads first (overlap with weight staging) ----
    stage_async(bufs[0], aX, tid, x0, y0);   // group: a-tile
    stage_async(bufs[1], hX, tid, x0, y0);   // group: h-tile

    // ---- weight + param staging ----
    for (int i=tid; i<1800; i+=256){
        int o = i/180, r = i - o*180, c = r/9, k = r - c*9;
        s_wdt[(c*9+k)*WPAD + o] = w_decomp[i];
        s_wct[(c*9+k)*WPAD + o] = wc[i];
    }
    if (tid < 10){
        s_par[P_GD+tid]=g_decomp[tid]; s_par[P_BED+tid]=be_decomp[tid];
        s_par[P_GC+tid]=gcv[tid];      s_par[P_BEC+tid]=becv[tid];
        s_par[P_GG+tid]=ggv[tid];      s_par[P_BEG+tid]=bev[tid];
    }
    if (tid >= 32 && tid < 72) s_par[P_WG + tid-32] = wgv[tid-32];
    if (tid == 72) { s_par[P_BG]=bgv[0]; s_par[P_BG+1]=bgv[1]; }
    for (int i=tid; i<200; i+=256) s_par[P_WC+i] = wcv[i];

    cp_wait0();
    __syncthreads();

    // ---- issue pm0 -> T2, then compute the three h/a passes ----
    stage_async(bufs[2], g_pm + (size_t)(pidx0*NB + b)*CHW, tid, x0, y0);

    float accDL[10], accDR[10];
    #pragma unroll
    for (int o=0;o<10;o++){ accDL[o]=0.0f; accDR[o]=0.0f; }
    conv_pass(accDL, accDR, bufs[0], s_wdt, tx, ty);        // w_decomp[:, 0:10] * (f*att)
    conv_pass(accDL, accDR, bufs[1], s_wdt + 1080, tx, ty); // w_decomp[:, 10:20] * h

    float msgL[10], msgR[10];
    #pragma unroll
    for (int o=0;o<10;o++){
        msgL[o] = fmaxf(fmaf(s_par[P_GD+o], accDL[o], s_par[P_BED+o]), 0.0f);
        msgR[o] = fmaxf(fmaf(s_par[P_GD+o], accDR[o], s_par[P_BED+o]), 0.0f);
    }

    float accAL[10], accAR[10];
    #pragma unroll
    for (int o=0;o<10;o++){ accAL[o]=0.0f; accAR[o]=0.0f; }
    conv_pass(accAL, accAR, bufs[1], s_wct, tx, ty);        // shared: w_c[:, 0:10] * h

    // ---- part loop: tile for part p lives in bufs[(2+p)%3]; prefetch p+1 into bufs[p%3] ----
    for (int part=0; part<nparts; part++){
        cp_wait0();            // drains the load for THIS part (only one group outstanding)
        __syncthreads();       // all threads' copies visible; all done reading recycled buffer
        if (part+1 < nparts)
            stage_async(bufs[part%3], g_pm + (size_t)((pidx0+part+1)*NB + b)*CHW, tid, x0, y0);
        const float* cur = bufs[(2+part)%3];
        float aL[10], aR[10];
        #pragma unroll
        for (int o=0;o<10;o++){ aL[o]=accAL[o]; aR[o]=accAR[o]; }
        conv_pass(aL, aR, cur, s_wct + 1080, tx, ty);       // w_c[:, 10:20] * (p*map)
        #pragma unroll
        for (int o=0;o<10;o++){
            msgL[o] += fmaxf(fmaf(s_par[P_GC+o], aL[o], s_par[P_BEC+o]), 0.0f);
            msgR[o] += fmaxf(fmaf(s_par[P_GC+o], aR[o], s_par[P_BEC+o]), 0.0f);
        }
    }

    // ---------- GRU epilogue (2 px); h center re-read from global (L2-hot) ----------
    float hcenL[10], hcenR[10];
    {
        const float* hc = hX + (size_t)(y0+ty)*NW + x0 + tx*2;
        #pragma unroll
        for (int ci=0; ci<10; ci++){
            float2 hv = *(const float2*)(hc + (size_t)ci*HW);
            hcenL[ci]=hv.x; hcenR[ci]=hv.y;
        }
    }

    float g0L=s_par[P_BG], g1L=s_par[P_BG+1], g0R=s_par[P_BG], g1R=s_par[P_BG+1];
    #pragma unroll
    for (int c=0;c<10;c++){
        float wm0=s_par[P_WG+c], wh0=s_par[P_WG+10+c], wm1=s_par[P_WG+20+c], wh1=s_par[P_WG+30+c];
        g0L = fmaf(wm0, msgL[c], g0L); g0L = fmaf(wh0, hcenL[c], g0L);
        g1L = fmaf(wm1, msgL[c], g1L); g1L = fmaf(wh1, hcenL[c], g1L);
        g0R = fmaf(wm0, msgR[c], g0R); g0R = fmaf(wh0, hcenR[c], g0R);
        g1R = fmaf(wm1, msgR[c], g1R); g1R = fmaf(wh1, hcenR[c], g1R);
    }
    float rL = sigmoidf_(g0L), uL = sigmoidf_(g1L);
    float rR = sigmoidf_(g0R), uR = sigmoidf_(g1R);
    float rhL[10], rhR[10];
    #pragma unroll
    for (int c=0;c<10;c++){ rhL[c]=rL*hcenL[c]; rhR[c]=rR*hcenR[c]; }

    float* op = outp + (size_t)(y0+ty)*NW + x0 + tx*2;
    #pragma unroll
    for (int o=0;o<10;o++){
        float sL = 0.0f, sR = 0.0f;
        #pragma unroll
        for (int c=0;c<10;c++){
            float wm = s_par[P_WC + o*20 + c];
            float wh = s_par[P_WC + o*20 + 10 + c];
            sL = fmaf(wm, msgL[c], sL); sL = fmaf(wh, rhL[c], sL);
            sR = fmaf(wm, msgR[c], sR); sR = fmaf(wh, rhR[c], sR);
        }
        float cnL = fmaf(s_par[P_GG+o], sL, s_par[P_BEG+o]);
        float cnR = fmaf(s_par[P_GG+o], sR, s_par[P_BEG+o]);
        cnL = cnL > 0.0f ? cnL : 0.01f*cnL;
        cnR = cnR > 0.0f ? cnR : 0.01f*cnR;
        float2 outv;
        outv.x = (1.0f-uL)*hcenL[o] + uL*cnL;
        outv.y = (1.0f-uR)*hcenR[o] + uR*cnR;
        *(float2*)(op + (size_t)o*HW) = outv;
    }
}

// ================= launcher =================
extern "C" void kernel_launch(void* const* d_in, const int* in_sizes, int n_in,
                              void* d_out, int out_size)
{
    const float* f_nodes  = (const float*)d_in[0];
    const float* h_nodes  = (const float*)d_in[1];
    const float* p_nodes  = (const float*)d_in[2];
    const float* w_dmap   = (const float*)d_in[4];
    const float* b_dmap   = (const float*)d_in[5];
    const float* w_decomp = (const float*)d_in[6];
    const float* g_decomp = (const float*)d_in[7];
    const float* be_decomp= (const float*)d_in[8];
    const float* w_cau    = (const float*)d_in[9];
    const float* b_cau    = (const float*)d_in[10];
    const float* w_cal    = (const float*)d_in[11];
    const float* b_cal    = (const float*)d_in[12];
    const float* w_cu     = (const float*)d_in[13];
    const float* g_cu     = (const float*)d_in[14];
    const float* be_cu    = (const float*)d_in[15];
    const float* w_cl     = (const float*)d_in[16];
    const float* g_cl     = (const float*)d_in[17];
    const float* be_cl    = (const float*)d_in[18];
    const float* wg_u     = (const float*)d_in[19];
    const float* bg_u     = (const float*)d_in[20];
    const float* wc_u     = (const float*)d_in[21];
    const float* g_u      = (const float*)d_in[22];
    const float* be_u     = (const float*)d_in[23];
    const float* wg_l     = (const float*)d_in[24];
    const float* bg_l     = (const float*)d_in[25];
    const float* wc_l     = (const float*)d_in[26];
    const float* g_l      = (const float*)d_in[27];
    const float* be_l     = (const float*)d_in[28];

    float* out        = (float*)d_out;
    float* out_decomp = out + (size_t)3*NB*CHW;
    float* out_cmu    = out_decomp + (size_t)NB*3*HW;
    float* out_cml    = out_cmu + (size_t)NB*HW;

    k1_pointwise<<<NB*HW/1024, 256>>>(f_nodes, h_nodes, p_nodes,
                                      w_dmap, b_dmap, w_cau, b_cau, w_cal, b_cal,
                                      out_decomp, out_cmu, out_cml, out);

    static int smem_set = 0;
    if (!smem_set){
        cudaFuncSetAttribute(k2_conv, cudaFuncAttributeMaxDynamicSharedMemorySize, SMEM_BYTES);
        smem_set = 1;
    }
    dim3 g2(NW/OUT_W, NH/OUT_H, 2*NB), b2(16, 16);
    k2_conv<<<g2, b2, SMEM_BYTES>>>(h_nodes,
                                    w_decomp, g_decomp, be_decomp,
                                    w_cu, g_cu, be_cu,
                                    w_cl, g_cl, be_cl,
                                    wg_u, bg_u, wc_u, g_u, be_u,
                                    wg_l, bg_l, wc_l, g_l, be_l,
                                    out);
}